// round 6
// baseline (speedup 1.0000x reference)
#include <cuda_runtime.h>

#define EPSF 1e-5f

// Precomputed categorical results: Y[g][cat][o] = sigmoid(GN(emb[g*100+cat]) @ W_cat[g] + b_cat[g])
__device__ __align__(16) float d_Y[100 * 100 * 128];
// Transposed num weights: WnumT[o][i] = W_num[i][o]  (128 x 100)
__device__ __align__(16) float d_WnumT[128 * 100];
__device__ __align__(16) float d_bnumT[128 * 100];

__device__ __forceinline__ float sigf(float x) { return 1.0f / (1.0f + __expf(-x)); }

__device__ __forceinline__ float sig_tanh(float x) {
    // sigmoid(x) = 0.5*tanh(0.5x) + 0.5 ; MUFU.TANH
    float t;
    asm("tanh.approx.f32 %0, %1;" : "=f"(t) : "f"(0.5f * x));
    return fmaf(0.5f, t, 0.5f);
}

// ---------------- Kernel 0: transpose W_num/b_num ----------------
__global__ __launch_bounds__(256) void transpose_wb(
    const float* __restrict__ W_num, const float* __restrict__ b_num)
{
    int idx = blockIdx.x * 256 + threadIdx.x;
    if (idx < 12800) {
        int o = idx / 100;
        int i = idx - o * 100;
        d_WnumT[idx] = W_num[i * 128 + o];
        d_bnumT[idx] = b_num[i * 128 + o];
    }
}

// ---------------- Kernel 1: precompute Y ----------------
__global__ __launch_bounds__(128) void precompute_Y(
    const float* __restrict__ emb_table,
    const float* __restrict__ gn_w, const float* __restrict__ gn_b,
    const float* __restrict__ W_cat, const float* __restrict__ b_cat)
{
    extern __shared__ float sh[];
    float* Wsh = sh;                 // 128*128
    float* Esh = sh + 128 * 128;     // 25 * 132
    __shared__ float s_mean[25], s_rstd[25];

    const int g    = blockIdx.x;
    const int tile = blockIdx.y;
    const int tid  = threadIdx.x;

    const float4* Wg4 = reinterpret_cast<const float4*>(W_cat + (size_t)g * 16384);
    float4* Wsh4 = reinterpret_cast<float4*>(Wsh);
    #pragma unroll
    for (int i = 0; i < 32; ++i) Wsh4[i * 128 + tid] = Wg4[i * 128 + tid];

    const int row0 = tile * 25;
    #pragma unroll 5
    for (int r = 0; r < 25; ++r)
        Esh[r * 132 + tid] = emb_table[((size_t)(g * 100 + row0 + r)) * 128 + tid];
    __syncthreads();

    if (tid < 25) {
        float s = 0.f, s2 = 0.f;
        #pragma unroll 8
        for (int k = 0; k < 128; ++k) {
            float v = Esh[tid * 132 + k];
            s += v; s2 += v * v;
        }
        float m   = s  * 0.0078125f;
        float var = fmaxf(s2 * 0.0078125f - m * m, 0.f);
        s_mean[tid] = m;
        s_rstd[tid] = rsqrtf(var + EPSF);
    }
    __syncthreads();

    const float gw = gn_w[g * 128 + tid];
    const float gb = gn_b[g * 128 + tid];
    #pragma unroll 5
    for (int r = 0; r < 25; ++r)
        Esh[r * 132 + tid] = fmaf((Esh[r * 132 + tid] - s_mean[r]) * s_rstd[r], gw, gb);
    __syncthreads();

    float acc[25];
    const float bc = b_cat[g * 128 + tid];
    #pragma unroll
    for (int r = 0; r < 25; ++r) acc[r] = bc;

    for (int k4 = 0; k4 < 32; ++k4) {
        float w0 = Wsh[(k4 * 4 + 0) * 128 + tid];
        float w1 = Wsh[(k4 * 4 + 1) * 128 + tid];
        float w2 = Wsh[(k4 * 4 + 2) * 128 + tid];
        float w3 = Wsh[(k4 * 4 + 3) * 128 + tid];
        #pragma unroll
        for (int r = 0; r < 25; ++r) {
            float4 e = *reinterpret_cast<const float4*>(&Esh[r * 132 + k4 * 4]);
            acc[r] = fmaf(e.x, w0, acc[r]);
            acc[r] = fmaf(e.y, w1, acc[r]);
            acc[r] = fmaf(e.z, w2, acc[r]);
            acc[r] = fmaf(e.w, w3, acc[r]);
        }
    }
    #pragma unroll 5
    for (int r = 0; r < 25; ++r)
        d_Y[((size_t)(g * 100 + row0 + r)) * 128 + tid] = sigf(acc[r]);
}

// ---------------- Kernel 2: fused gather + num branch ----------------
// Block = 8 samples, full 128 cond, 512 threads.
// Phase B: W/b read ONCE per block, reused across 8 samples (L2 traffic /8).
// Phase A: lane pairs read adjacent 16B of one Y row -> full 32B sectors;
//          transposed STS stays bank-conflict-free (banks = 16*o4_lo + g).
// Output via __stcs streaming stores to keep d_Y/W resident in L2.
__global__ __launch_bounds__(512, 3) void fuse_main(
    const float* __restrict__ x_num, const int* __restrict__ x_cat,
    float* __restrict__ out)
{
    __shared__ float sh[128 * 100];   // 51.2 KB transposed cat staging
    __shared__ int   s_cat[8 * 100];
    __shared__ float s_num[8 * 100];

    const int tid = threadIdx.x;
    const int b0  = blockIdx.x * 8;

    #pragma unroll 2
    for (int i = tid; i < 800; i += 512) {
        s_cat[i] = x_cat[b0 * 100 + i];
        s_num[i] = x_num[b0 * 100 + i];
    }
    __syncthreads();

    // ---- Phase B: num branch, all 8 samples, W/b in registers ----
    for (int idx = tid; idx < 3200; idx += 512) {
        int o  = idx / 25;
        int i4 = idx - o * 25;
        float4 w  = *reinterpret_cast<const float4*>(&d_WnumT[o * 100 + i4 * 4]);
        float4 bb = *reinterpret_cast<const float4*>(&d_bnumT[o * 100 + i4 * 4]);
        #pragma unroll
        for (int s = 0; s < 8; ++s) {
            float4 xs = *reinterpret_cast<const float4*>(&s_num[s * 100 + i4 * 4]);
            float4 r;
            r.x = sig_tanh(fmaf(xs.x, w.x, bb.x));
            r.y = sig_tanh(fmaf(xs.y, w.y, bb.y));
            r.z = sig_tanh(fmaf(xs.z, w.z, bb.z));
            r.w = sig_tanh(fmaf(xs.w, w.w, bb.w));
            __stcs(reinterpret_cast<float4*>(
                &out[(size_t)(b0 + s) * 25600 + (size_t)o * 200 + i4 * 4]), r);
        }
    }

    // ---- Per-sample cat gather + transpose ----
    for (int s = 0; s < 8; ++s) {
        const int* cats = &s_cat[s * 100];
        // Phase A: gather Y rows into transposed staging.
        // idx = o4_hi*200 + g*2 + o4_lo : lane pairs share a row (32B sectors)
        for (int idx = tid; idx < 3200; idx += 512) {
            int o4h = idx / 200;
            int rem = idx - o4h * 200;
            int g   = rem >> 1;
            int o4  = o4h * 2 + (rem & 1);
            float4 v = *reinterpret_cast<const float4*>(
                &d_Y[(g * 100 + cats[g]) * 128 + o4 * 4]);
            sh[(o4 * 4 + 0) * 100 + g] = v.x;
            sh[(o4 * 4 + 1) * 100 + g] = v.y;
            sh[(o4 * 4 + 2) * 100 + g] = v.z;
            sh[(o4 * 4 + 3) * 100 + g] = v.w;
        }
        __syncthreads();
        // Phase C: vectorized LDS.128 + streaming STG.128
        float* outb = out + (size_t)(b0 + s) * 25600 + 100;
        for (int idx = tid; idx < 3200; idx += 512) {
            int o  = idx / 25;
            int g4 = idx - o * 25;
            float4 v = *reinterpret_cast<const float4*>(&sh[o * 100 + g4 * 4]);
            __stcs(reinterpret_cast<float4*>(&outb[(size_t)o * 200 + g4 * 4]), v);
        }
        __syncthreads();
    }
}

extern "C" void kernel_launch(void* const* d_in, const int* in_sizes, int n_in,
                              void* d_out, int out_size) {
    const float* x_num = (const float*)d_in[0];
    const int*   x_cat = (const int*)  d_in[1];
    const float* W_num = (const float*)d_in[2];
    const float* b_num = (const float*)d_in[3];
    const float* emb   = (const float*)d_in[4];
    const float* gn_w  = (const float*)d_in[5];
    const float* gn_b  = (const float*)d_in[6];
    const float* W_cat = (const float*)d_in[7];
    const float* b_cat = (const float*)d_in[8];
    float* out = (float*)d_out;

    const int smem_pre = (128 * 128 + 25 * 132) * 4;
    cudaFuncSetAttribute(precompute_Y, cudaFuncAttributeMaxDynamicSharedMemorySize, smem_pre);

    transpose_wb<<<50, 256>>>(W_num, b_num);
    precompute_Y<<<dim3(100, 4), 128, smem_pre>>>(emb, gn_w, gn_b, W_cat, b_cat);
    fuse_main<<<512, 512>>>(x_num, x_cat, out);
}

// round 7
// speedup vs baseline: 1.0860x; 1.0860x over previous
#include <cuda_runtime.h>

#define EPSF 1e-5f

// Precomputed categorical results: Y[g][cat][o] = sigmoid(GN(emb[g*100+cat]) @ W_cat[g] + b_cat[g])
__device__ __align__(16) float d_Y[100 * 100 * 128];
// Transposed num weights: WnumT[o][i] = W_num[i][o]  (128 x 100)
__device__ __align__(16) float d_WnumT[128 * 100];
__device__ __align__(16) float d_bnumT[128 * 100];

__device__ __forceinline__ float sigf(float x) { return 1.0f / (1.0f + __expf(-x)); }

__device__ __forceinline__ float sig_tanh(float x) {
    // sigmoid(x) = 0.5*tanh(0.5x) + 0.5 ; MUFU.TANH
    float t;
    asm("tanh.approx.f32 %0, %1;" : "=f"(t) : "f"(0.5f * x));
    return fmaf(0.5f, t, 0.5f);
}

// ---------------- Kernel 1: precompute Y (+ folded W transpose) ----------------
// grid (100, 5): tile 0..3 = Y precompute; tile 4 = W_num/b_num transpose.
__global__ __launch_bounds__(128) void precompute_Y(
    const float* __restrict__ emb_table,
    const float* __restrict__ gn_w, const float* __restrict__ gn_b,
    const float* __restrict__ W_cat, const float* __restrict__ b_cat,
    const float* __restrict__ W_num, const float* __restrict__ b_num)
{
    extern __shared__ float sh[];
    float* Wsh = sh;                 // 128*128
    float* Esh = sh + 128 * 128;     // 25 * 132
    __shared__ float s_mean[25], s_rstd[25];

    const int g    = blockIdx.x;
    const int tile = blockIdx.y;
    const int tid  = threadIdx.x;

    if (tile == 4) {                 // transpose branch: 100 blocks x 128 thr = 12800
        int idx = g * 128 + tid;
        int o = idx / 100;
        int i = idx - o * 100;
        d_WnumT[idx] = W_num[i * 128 + o];
        d_bnumT[idx] = b_num[i * 128 + o];
        return;
    }

    const float4* Wg4 = reinterpret_cast<const float4*>(W_cat + (size_t)g * 16384);
    float4* Wsh4 = reinterpret_cast<float4*>(Wsh);
    #pragma unroll
    for (int i = 0; i < 32; ++i) Wsh4[i * 128 + tid] = Wg4[i * 128 + tid];

    const int row0 = tile * 25;
    #pragma unroll 5
    for (int r = 0; r < 25; ++r)
        Esh[r * 132 + tid] = emb_table[((size_t)(g * 100 + row0 + r)) * 128 + tid];
    __syncthreads();

    if (tid < 25) {
        float s = 0.f, s2 = 0.f;
        #pragma unroll 8
        for (int k = 0; k < 128; ++k) {
            float v = Esh[tid * 132 + k];
            s += v; s2 += v * v;
        }
        float m   = s  * 0.0078125f;
        float var = fmaxf(s2 * 0.0078125f - m * m, 0.f);
        s_mean[tid] = m;
        s_rstd[tid] = rsqrtf(var + EPSF);
    }
    __syncthreads();

    const float gw = gn_w[g * 128 + tid];
    const float gb = gn_b[g * 128 + tid];
    #pragma unroll 5
    for (int r = 0; r < 25; ++r)
        Esh[r * 132 + tid] = fmaf((Esh[r * 132 + tid] - s_mean[r]) * s_rstd[r], gw, gb);
    __syncthreads();

    float acc[25];
    const float bc = b_cat[g * 128 + tid];
    #pragma unroll
    for (int r = 0; r < 25; ++r) acc[r] = bc;

    for (int k4 = 0; k4 < 32; ++k4) {
        float w0 = Wsh[(k4 * 4 + 0) * 128 + tid];
        float w1 = Wsh[(k4 * 4 + 1) * 128 + tid];
        float w2 = Wsh[(k4 * 4 + 2) * 128 + tid];
        float w3 = Wsh[(k4 * 4 + 3) * 128 + tid];
        #pragma unroll
        for (int r = 0; r < 25; ++r) {
            float4 e = *reinterpret_cast<const float4*>(&Esh[r * 132 + k4 * 4]);
            acc[r] = fmaf(e.x, w0, acc[r]);
            acc[r] = fmaf(e.y, w1, acc[r]);
            acc[r] = fmaf(e.z, w2, acc[r]);
            acc[r] = fmaf(e.w, w3, acc[r]);
        }
    }
    #pragma unroll 5
    for (int r = 0; r < 25; ++r)
        d_Y[((size_t)(g * 100 + row0 + r)) * 128 + tid] = sigf(acc[r]);
}

// ---------------- Kernel 2: fused gather + num branch ----------------
// grid (2048 sample-pairs, 2 cond-halves), 512 threads, 4 blocks/SM (full occ).
// R5 structure (all phases parallel, plain stores), with W/b float4s loaded
// once per thread and reused for 2 samples -> W/b L2 traffic halved.
__global__ __launch_bounds__(512, 4) void fuse_main(
    const float* __restrict__ x_num, const int* __restrict__ x_cat,
    float* __restrict__ out)
{
    __shared__ __align__(16) float sh[2 * 64 * 100];   // 51.2 KB
    __shared__ __align__(16) int   s_cat[200];
    __shared__ __align__(16) float s_num[200];

    const int tid = threadIdx.x;
    const int b0  = blockIdx.x * 2;
    const int ob  = blockIdx.y * 64;

    if (tid < 200)      s_cat[tid]       = x_cat[b0 * 100 + tid];
    else if (tid < 400) s_num[tid - 200] = x_num[b0 * 100 + (tid - 200)];
    __syncthreads();

    // Phase B: num branch, W/b loaded once, applied to both samples.
    #pragma unroll 2
    for (int idx = tid; idx < 1600; idx += 512) {
        int o  = idx / 25;
        int i4 = idx - o * 25;
        float4 w  = *reinterpret_cast<const float4*>(&d_WnumT[(ob + o) * 100 + i4 * 4]);
        float4 bb = *reinterpret_cast<const float4*>(&d_bnumT[(ob + o) * 100 + i4 * 4]);
        #pragma unroll
        for (int s = 0; s < 2; ++s) {
            float4 xs = *reinterpret_cast<const float4*>(&s_num[s * 100 + i4 * 4]);
            float4 r;
            r.x = sig_tanh(fmaf(xs.x, w.x, bb.x));
            r.y = sig_tanh(fmaf(xs.y, w.y, bb.y));
            r.z = sig_tanh(fmaf(xs.z, w.z, bb.z));
            r.w = sig_tanh(fmaf(xs.w, w.w, bb.w));
            *reinterpret_cast<float4*>(
                &out[(size_t)(b0 + s) * 25600 + (size_t)(ob + o) * 200 + i4 * 4]) = r;
        }
    }

    // Phase A: gather cat rows from Y into transposed staging, both samples.
    #pragma unroll 2
    for (int idx = tid; idx < 3200; idx += 512) {
        int s  = (idx >= 1600) ? 1 : 0;
        int r  = idx - s * 1600;
        int o4 = r / 100;
        int g  = r - o4 * 100;
        float4 v = *reinterpret_cast<const float4*>(
            &d_Y[(g * 100 + s_cat[s * 100 + g]) * 128 + ob + o4 * 4]);
        float* dst = &sh[s * 6400 + (o4 * 4) * 100 + g];
        dst[0]   = v.x;
        dst[100] = v.y;
        dst[200] = v.z;
        dst[300] = v.w;
    }
    __syncthreads();

    // Phase C: cat output, vectorized LDS.128 + STG.128, both samples.
    #pragma unroll 2
    for (int idx = tid; idx < 3200; idx += 512) {
        int s  = (idx >= 1600) ? 1 : 0;
        int r  = idx - s * 1600;
        int o  = r / 25;
        int g4 = r - o * 25;
        float4 v = *reinterpret_cast<const float4*>(&sh[s * 6400 + o * 100 + g4 * 4]);
        *reinterpret_cast<float4*>(
            &out[(size_t)(b0 + s) * 25600 + (size_t)(ob + o) * 200 + 100 + g4 * 4]) = v;
    }
}

extern "C" void kernel_launch(void* const* d_in, const int* in_sizes, int n_in,
                              void* d_out, int out_size) {
    const float* x_num = (const float*)d_in[0];
    const int*   x_cat = (const int*)  d_in[1];
    const float* W_num = (const float*)d_in[2];
    const float* b_num = (const float*)d_in[3];
    const float* emb   = (const float*)d_in[4];
    const float* gn_w  = (const float*)d_in[5];
    const float* gn_b  = (const float*)d_in[6];
    const float* W_cat = (const float*)d_in[7];
    const float* b_cat = (const float*)d_in[8];
    float* out = (float*)d_out;

    const int smem_pre = (128 * 128 + 25 * 132) * 4;
    cudaFuncSetAttribute(precompute_Y, cudaFuncAttributeMaxDynamicSharedMemorySize, smem_pre);

    precompute_Y<<<dim3(100, 5), 128, smem_pre>>>(emb, gn_w, gn_b, W_cat, b_cat, W_num, b_num);
    fuse_main<<<dim3(2048, 2), 512>>>(x_num, x_cat, out);
}

// round 9
// speedup vs baseline: 1.4409x; 1.3268x over previous
#include <cuda_runtime.h>

#define EPSF 1e-5f

// Precomputed categorical results: Y[g][cat][o] = sigmoid(GN(emb[g*100+cat]) @ W_cat[g] + b_cat[g])
__device__ __align__(16) float d_Y[100 * 100 * 128];
// Transposed num weights: WnumT[o][i] = W_num[i][o]  (128 x 100)
__device__ __align__(16) float d_WnumT[128 * 100];
__device__ __align__(16) float d_bnumT[128 * 100];

__device__ __forceinline__ float sigf(float x) { return 1.0f / (1.0f + __expf(-x)); }

__device__ __forceinline__ float sig_tanh(float x) {
    // sigmoid(x) = 0.5*tanh(0.5x) + 0.5 ; MUFU.TANH
    float t;
    asm("tanh.approx.f32 %0, %1;" : "=f"(t) : "f"(0.5f * x));
    return fmaf(0.5f, t, 0.5f);
}

// ---------------- Kernel 1: precompute Y (+ folded W transpose) ----------------
// grid (100, 5): tile 0..3 = Y precompute; tile 4 = W_num/b_num transpose.
// W_cat streamed from L2 (read 4x = 25.6 MB total, trivial); smem only holds
// the 25 embedding rows -> 13.3 KB -> high occupancy, FMA-bound.
__global__ __launch_bounds__(128) void precompute_Y(
    const float* __restrict__ emb_table,
    const float* __restrict__ gn_w, const float* __restrict__ gn_b,
    const float* __restrict__ W_cat, const float* __restrict__ b_cat,
    const float* __restrict__ W_num, const float* __restrict__ b_num)
{
    __shared__ __align__(16) float Esh[25 * 132];
    __shared__ float s_mean[25], s_rstd[25];

    const int g    = blockIdx.x;
    const int tile = blockIdx.y;
    const int tid  = threadIdx.x;

    if (tile == 4) {                 // transpose branch: 100 blocks x 128 thr
        int idx = g * 128 + tid;
        int o = idx / 100;
        int i = idx - o * 100;
        d_WnumT[idx] = W_num[i * 128 + o];
        d_bnumT[idx] = b_num[i * 128 + o];
        return;
    }

    const int row0 = tile * 25;
    #pragma unroll 5
    for (int r = 0; r < 25; ++r)
        Esh[r * 132 + tid] = emb_table[((size_t)(g * 100 + row0 + r)) * 128 + tid];
    __syncthreads();

    if (tid < 25) {
        float s = 0.f, s2 = 0.f;
        #pragma unroll 8
        for (int k = 0; k < 128; ++k) {
            float v = Esh[tid * 132 + k];
            s += v; s2 += v * v;
        }
        float m   = s  * 0.0078125f;
        float var = fmaxf(s2 * 0.0078125f - m * m, 0.f);
        s_mean[tid] = m;
        s_rstd[tid] = rsqrtf(var + EPSF);
    }
    __syncthreads();

    const float gw = gn_w[g * 128 + tid];
    const float gb = gn_b[g * 128 + tid];
    #pragma unroll 5
    for (int r = 0; r < 25; ++r)
        Esh[r * 132 + tid] = fmaf((Esh[r * 132 + tid] - s_mean[r]) * s_rstd[r], gw, gb);
    __syncthreads();

    float acc[25];
    const float bc = b_cat[g * 128 + tid];
    #pragma unroll
    for (int r = 0; r < 25; ++r) acc[r] = bc;

    const float* Wg = W_cat + (size_t)g * 16384 + tid;   // column tid, stride 128
    #pragma unroll 2
    for (int k4 = 0; k4 < 32; ++k4) {
        float w0 = Wg[(k4 * 4 + 0) * 128];
        float w1 = Wg[(k4 * 4 + 1) * 128];
        float w2 = Wg[(k4 * 4 + 2) * 128];
        float w3 = Wg[(k4 * 4 + 3) * 128];
        #pragma unroll
        for (int r = 0; r < 25; ++r) {
            float4 e = *reinterpret_cast<const float4*>(&Esh[r * 132 + k4 * 4]);  // broadcast
            acc[r] = fmaf(e.x, w0, acc[r]);
            acc[r] = fmaf(e.y, w1, acc[r]);
            acc[r] = fmaf(e.z, w2, acc[r]);
            acc[r] = fmaf(e.w, w3, acc[r]);
        }
    }
    #pragma unroll 5
    for (int r = 0; r < 25; ++r)
        d_Y[((size_t)(g * 100 + row0 + r)) * 128 + tid] = sigf(acc[r]);
}

// ---------------- Kernel 2: fused gather + num branch ----------------
// grid 2048 (2 samples/block), 512 threads. NO smem transpose:
// cat path does a 4x4 register transpose per thread:
//   4x LDG.128 (4 Y rows, 16B each, warp-coalesced) -> 4x STG.128 direct to out
//   (lanes 0..24 cover one 400B output row segment contiguously).
// num path: W/b float4 loaded once, reused for both samples.
__global__ __launch_bounds__(512, 3) void fuse_main(
    const float* __restrict__ x_num, const int* __restrict__ x_cat,
    float* __restrict__ out)
{
    __shared__ int   s_cat[200];
    __shared__ float s_num[200];

    const int tid = threadIdx.x;
    const int b0  = blockIdx.x * 2;

    if (tid < 200)      s_cat[tid]       = x_cat[b0 * 100 + tid];
    else if (tid < 400) s_num[tid - 200] = x_num[b0 * 100 + (tid - 200)];
    __syncthreads();

    // ---- num branch: 128 o x 25 i-quads, W/b reused across 2 samples ----
    #pragma unroll 2
    for (int idx = tid; idx < 3200; idx += 512) {
        int o  = idx / 25;
        int i4 = idx - o * 25;
        float4 w  = *reinterpret_cast<const float4*>(&d_WnumT[o * 100 + i4 * 4]);
        float4 bb = *reinterpret_cast<const float4*>(&d_bnumT[o * 100 + i4 * 4]);
        #pragma unroll
        for (int s = 0; s < 2; ++s) {
            float4 xs = *reinterpret_cast<const float4*>(&s_num[s * 100 + i4 * 4]);
            float4 r;
            r.x = sig_tanh(fmaf(xs.x, w.x, bb.x));
            r.y = sig_tanh(fmaf(xs.y, w.y, bb.y));
            r.z = sig_tanh(fmaf(xs.z, w.z, bb.z));
            r.w = sig_tanh(fmaf(xs.w, w.w, bb.w));
            *reinterpret_cast<float4*>(
                &out[(size_t)(b0 + s) * 25600 + (size_t)o * 200 + i4 * 4]) = r;
        }
    }

    // ---- cat branch: 2 samples x 32 o-quads x 25 g-quads ----
    for (int idx = tid; idx < 1600; idx += 512) {
        int t  = idx / 25;            // 0..63 = s*32 + o_quad
        int g4 = idx - t * 25;
        int s  = t >> 5;
        int oq = (t & 31) * 4;        // o base (0,4,...,124)
        const int* cats = &s_cat[s * 100];
        int g = g4 * 4;

        float4 v0 = *reinterpret_cast<const float4*>(&d_Y[((g + 0) * 100 + cats[g + 0]) * 128 + oq]);
        float4 v1 = *reinterpret_cast<const float4*>(&d_Y[((g + 1) * 100 + cats[g + 1]) * 128 + oq]);
        float4 v2 = *reinterpret_cast<const float4*>(&d_Y[((g + 2) * 100 + cats[g + 2]) * 128 + oq]);
        float4 v3 = *reinterpret_cast<const float4*>(&d_Y[((g + 3) * 100 + cats[g + 3]) * 128 + oq]);

        float* ob = &out[(size_t)(b0 + s) * 25600 + (size_t)oq * 200 + 100 + g];
        float4 r0 = make_float4(v0.x, v1.x, v2.x, v3.x);
        float4 r1 = make_float4(v0.y, v1.y, v2.y, v3.y);
        float4 r2 = make_float4(v0.z, v1.z, v2.z, v3.z);
        float4 r3 = make_float4(v0.w, v1.w, v2.w, v3.w);
        *reinterpret_cast<float4*>(&ob[0])   = r0;
        *reinterpret_cast<float4*>(&ob[200]) = r1;
        *reinterpret_cast<float4*>(&ob[400]) = r2;
        *reinterpret_cast<float4*>(&ob[600]) = r3;
    }
}

extern "C" void kernel_launch(void* const* d_in, const int* in_sizes, int n_in,
                              void* d_out, int out_size) {
    const float* x_num = (const float*)d_in[0];
    const int*   x_cat = (const int*)  d_in[1];
    const float* W_num = (const float*)d_in[2];
    const float* b_num = (const float*)d_in[3];
    const float* emb   = (const float*)d_in[4];
    const float* gn_w  = (const float*)d_in[5];
    const float* gn_b  = (const float*)d_in[6];
    const float* W_cat = (const float*)d_in[7];
    const float* b_cat = (const float*)d_in[8];
    float* out = (float*)d_out;

    precompute_Y<<<dim3(100, 5), 128>>>(emb, gn_w, gn_b, W_cat, b_cat, W_num, b_num);
    fuse_main<<<2048, 512>>>(x_num, x_cat, out);
}

// round 11
// speedup vs baseline: 1.7192x; 1.1931x over previous
#include <cuda_runtime.h>

#define EPSF 1e-5f

// Precomputed categorical results: Y[g][cat][o] = sigmoid(GN(emb[g*100+cat]) @ W_cat[g] + b_cat[g])
__device__ __align__(16) float d_Y[100 * 100 * 128];
// Transposed num weights: WnumT[o][i] = W_num[i][o]  (128 x 100)
__device__ __align__(16) float d_WnumT[128 * 100];
__device__ __align__(16) float d_bnumT[128 * 100];

__device__ __forceinline__ float sigf(float x) { return 1.0f / (1.0f + __expf(-x)); }

__device__ __forceinline__ float sig_tanh(float x) {
    // sigmoid(x) = 0.5*tanh(0.5x) + 0.5 ; MUFU.TANH
    float t;
    asm("tanh.approx.f32 %0, %1;" : "=f"(t) : "f"(0.5f * x));
    return fmaf(0.5f, t, 0.5f);
}

// ---------------- Kernel 1: precompute Y (+ folded W transpose) ----------------
__global__ __launch_bounds__(128) void precompute_Y(
    const float* __restrict__ emb_table,
    const float* __restrict__ gn_w, const float* __restrict__ gn_b,
    const float* __restrict__ W_cat, const float* __restrict__ b_cat,
    const float* __restrict__ W_num, const float* __restrict__ b_num)
{
    __shared__ __align__(16) float Esh[25 * 132];
    __shared__ float s_mean[25], s_rstd[25];

    const int g    = blockIdx.x;
    const int tile = blockIdx.y;
    const int tid  = threadIdx.x;

    if (tile == 4) {
        int idx = g * 128 + tid;
        int o = idx / 100;
        int i = idx - o * 100;
        d_WnumT[idx] = W_num[i * 128 + o];
        d_bnumT[idx] = b_num[i * 128 + o];
        return;
    }

    const int row0 = tile * 25;
    #pragma unroll 5
    for (int r = 0; r < 25; ++r)
        Esh[r * 132 + tid] = emb_table[((size_t)(g * 100 + row0 + r)) * 128 + tid];
    __syncthreads();

    if (tid < 25) {
        float s = 0.f, s2 = 0.f;
        #pragma unroll 8
        for (int k = 0; k < 128; ++k) {
            float v = Esh[tid * 132 + k];
            s += v; s2 += v * v;
        }
        float m   = s  * 0.0078125f;
        float var = fmaxf(s2 * 0.0078125f - m * m, 0.f);
        s_mean[tid] = m;
        s_rstd[tid] = rsqrtf(var + EPSF);
    }
    __syncthreads();

    const float gw = gn_w[g * 128 + tid];
    const float gb = gn_b[g * 128 + tid];
    #pragma unroll 5
    for (int r = 0; r < 25; ++r)
        Esh[r * 132 + tid] = fmaf((Esh[r * 132 + tid] - s_mean[r]) * s_rstd[r], gw, gb);
    __syncthreads();

    float acc[25];
    const float bc = b_cat[g * 128 + tid];
    #pragma unroll
    for (int r = 0; r < 25; ++r) acc[r] = bc;

    const float* Wg = W_cat + (size_t)g * 16384 + tid;
    #pragma unroll 2
    for (int k4 = 0; k4 < 32; ++k4) {
        float w0 = Wg[(k4 * 4 + 0) * 128];
        float w1 = Wg[(k4 * 4 + 1) * 128];
        float w2 = Wg[(k4 * 4 + 2) * 128];
        float w3 = Wg[(k4 * 4 + 3) * 128];
        #pragma unroll
        for (int r = 0; r < 25; ++r) {
            float4 e = *reinterpret_cast<const float4*>(&Esh[r * 132 + k4 * 4]);
            acc[r] = fmaf(e.x, w0, acc[r]);
            acc[r] = fmaf(e.y, w1, acc[r]);
            acc[r] = fmaf(e.z, w2, acc[r]);
            acc[r] = fmaf(e.w, w3, acc[r]);
        }
    }
    #pragma unroll 5
    for (int r = 0; r < 25; ++r)
        d_Y[((size_t)(g * 100 + row0 + r)) * 128 + tid] = sigf(acc[r]);
}

// ---------------- Kernel 2: fused gather + num branch ----------------
// grid (2048 pairs, 2 cond-halves), 512 threads, 3 blocks/SM (reg-limited anyway).
// Gather: warp covers 4 Y rows/iter; 8 lanes x 16B = one full 128B line per row.
// Staging: stride 128 with XOR swizzle  col = g XOR (o & 28):
//   - STS (scalar, row quad): banks = (g XOR 4*jj) mod 32 -> all 32 distinct.
//   - LDS.128: swizzle is 4-aligned -> 16B alignment holds; 8-lane phases
//     permute consecutive float4s within a 128B span -> conflict-free.
__global__ __launch_bounds__(512, 3) void fuse_main(
    const float* __restrict__ x_num, const int* __restrict__ x_cat,
    float* __restrict__ out)
{
    extern __shared__ __align__(16) float sh[];   // [2][64][128] = 64 KB
    __shared__ int   s_cat[200];
    __shared__ float s_num[200];

    const int tid  = threadIdx.x;
    const int w    = tid >> 5;
    const int lane = tid & 31;
    const int jj   = lane & 7;     // 16B chunk within 128B line
    const int sub  = lane >> 3;    // row within quad
    const int b0   = blockIdx.x * 2;
    const int ob   = blockIdx.y * 64;

    if (tid < 200)      s_cat[tid]       = x_cat[b0 * 100 + tid];
    else if (tid < 400) s_num[tid - 200] = x_num[b0 * 100 + (tid - 200)];
    __syncthreads();

    // ---- Phase A: gather Y rows -> swizzled transposed staging ----
    // work item: (s, rq, h): 2 samples x 25 row-quads x 2 line-halves = 100
    for (int it = w; it < 100; it += 16) {
        int s   = it / 50;
        int rem = it - s * 50;
        int rq  = rem >> 1;
        int h   = rem & 1;
        int r   = rq * 4 + sub;            // g row 0..99
        int c   = h * 8 + jj;              // o-quad 0..15
        int cat = s_cat[s * 100 + r];
        float4 v = *reinterpret_cast<const float4*>(
            &d_Y[(r * 100 + cat) * 128 + ob + c * 4]);
        int col = r ^ (jj * 4);            // swizzle: (o>>2)&7 == jj for this quad
        float* dst = &sh[s * 8192 + (c * 4) * 128 + col];
        dst[0 * 128] = v.x;
        dst[1 * 128] = v.y;
        dst[2 * 128] = v.z;
        dst[3 * 128] = v.w;
    }

    // ---- Phase B: num branch, W/b loaded once, reused for 2 samples ----
    #pragma unroll 2
    for (int idx = tid; idx < 1600; idx += 512) {
        int o  = idx / 25;
        int i4 = idx - o * 25;
        float4 ww = *reinterpret_cast<const float4*>(&d_WnumT[(ob + o) * 100 + i4 * 4]);
        float4 bb = *reinterpret_cast<const float4*>(&d_bnumT[(ob + o) * 100 + i4 * 4]);
        #pragma unroll
        for (int s = 0; s < 2; ++s) {
            float4 xs = *reinterpret_cast<const float4*>(&s_num[s * 100 + i4 * 4]);
            float4 r;
            r.x = sig_tanh(fmaf(xs.x, ww.x, bb.x));
            r.y = sig_tanh(fmaf(xs.y, ww.y, bb.y));
            r.z = sig_tanh(fmaf(xs.z, ww.z, bb.z));
            r.w = sig_tanh(fmaf(xs.w, ww.w, bb.w));
            *reinterpret_cast<float4*>(
                &out[(size_t)(b0 + s) * 25600 + (size_t)(ob + o) * 200 + i4 * 4]) = r;
        }
    }
    __syncthreads();

    // ---- Phase C: cat output, swizzled LDS.128 + coalesced STG.128 ----
    #pragma unroll 2
    for (int idx = tid; idx < 3200; idx += 512) {
        int s  = (idx >= 1600) ? 1 : 0;
        int r  = idx - s * 1600;
        int o  = r / 25;
        int g4 = r - o * 25;
        int colb = (g4 * 4) ^ (o & 28);
        float4 v = *reinterpret_cast<const float4*>(&sh[s * 8192 + o * 128 + colb]);
        *reinterpret_cast<float4*>(
            &out[(size_t)(b0 + s) * 25600 + (size_t)(ob + o) * 200 + 100 + g4 * 4]) = v;
    }
}

extern "C" void kernel_launch(void* const* d_in, const int* in_sizes, int n_in,
                              void* d_out, int out_size) {
    const float* x_num = (const float*)d_in[0];
    const int*   x_cat = (const int*)  d_in[1];
    const float* W_num = (const float*)d_in[2];
    const float* b_num = (const float*)d_in[3];
    const float* emb   = (const float*)d_in[4];
    const float* gn_w  = (const float*)d_in[5];
    const float* gn_b  = (const float*)d_in[6];
    const float* W_cat = (const float*)d_in[7];
    const float* b_cat = (const float*)d_in[8];
    float* out = (float*)d_out;

    const int smem_main = 2 * 64 * 128 * 4;   // 65536 B
    cudaFuncSetAttribute(fuse_main, cudaFuncAttributeMaxDynamicSharedMemorySize, smem_main);

    precompute_Y<<<dim3(100, 5), 128>>>(emb, gn_w, gn_b, W_cat, b_cat, W_num, b_num);
    fuse_main<<<dim3(2048, 2), 512, smem_main>>>(x_num, x_cat, out);
}

// round 12
// speedup vs baseline: 1.9156x; 1.1143x over previous
#include <cuda_runtime.h>

#define EPSF 1e-5f

// Precomputed categorical results: Y[g][cat][o] = sigmoid(GN(emb[g*100+cat]) @ W_cat[g] + b_cat[g])
__device__ __align__(16) float d_Y[100 * 100 * 128];
// Transposed num weights: WnumT[o][i] = W_num[i][o]  (128 x 100)
__device__ __align__(16) float d_WnumT[128 * 100];
__device__ __align__(16) float d_bnumT[128 * 100];

__device__ __forceinline__ float sigf(float x) { return 1.0f / (1.0f + __expf(-x)); }

__device__ __forceinline__ float sig_tanh(float x) {
    // sigmoid(x) = 0.5*tanh(0.5x) + 0.5 ; MUFU.TANH
    float t;
    asm("tanh.approx.f32 %0, %1;" : "=f"(t) : "f"(0.5f * x));
    return fmaf(0.5f, t, 0.5f);
}

// ---------------- Kernel 1: precompute Y (+ folded W transpose) ----------------
// grid (100, 11): tile 0..9 = 10 Y rows each; tile 10 = W_num/b_num transpose.
__global__ __launch_bounds__(128) void precompute_Y(
    const float* __restrict__ emb_table,
    const float* __restrict__ gn_w, const float* __restrict__ gn_b,
    const float* __restrict__ W_cat, const float* __restrict__ b_cat,
    const float* __restrict__ W_num, const float* __restrict__ b_num)
{
    __shared__ __align__(16) float Esh[10 * 132];
    __shared__ float s_mean[10], s_rstd[10];

    const int g    = blockIdx.x;
    const int tile = blockIdx.y;
    const int tid  = threadIdx.x;

    if (tile == 10) {
        int idx = g * 128 + tid;
        int o = idx / 100;
        int i = idx - o * 100;
        d_WnumT[idx] = W_num[i * 128 + o];
        d_bnumT[idx] = b_num[i * 128 + o];
        return;
    }

    const int row0 = tile * 10;
    #pragma unroll
    for (int r = 0; r < 10; ++r)
        Esh[r * 132 + tid] = emb_table[((size_t)(g * 100 + row0 + r)) * 128 + tid];
    __syncthreads();

    if (tid < 10) {
        float s = 0.f, s2 = 0.f;
        #pragma unroll 8
        for (int k = 0; k < 128; ++k) {
            float v = Esh[tid * 132 + k];
            s += v; s2 += v * v;
        }
        float m   = s  * 0.0078125f;
        float var = fmaxf(s2 * 0.0078125f - m * m, 0.f);
        s_mean[tid] = m;
        s_rstd[tid] = rsqrtf(var + EPSF);
    }
    __syncthreads();

    const float gw = gn_w[g * 128 + tid];
    const float gb = gn_b[g * 128 + tid];
    #pragma unroll
    for (int r = 0; r < 10; ++r)
        Esh[r * 132 + tid] = fmaf((Esh[r * 132 + tid] - s_mean[r]) * s_rstd[r], gw, gb);
    __syncthreads();

    float acc[10];
    const float bc = b_cat[g * 128 + tid];
    #pragma unroll
    for (int r = 0; r < 10; ++r) acc[r] = bc;

    const float* Wg = W_cat + (size_t)g * 16384 + tid;
    #pragma unroll 4
    for (int k4 = 0; k4 < 32; ++k4) {
        float w0 = Wg[(k4 * 4 + 0) * 128];
        float w1 = Wg[(k4 * 4 + 1) * 128];
        float w2 = Wg[(k4 * 4 + 2) * 128];
        float w3 = Wg[(k4 * 4 + 3) * 128];
        #pragma unroll
        for (int r = 0; r < 10; ++r) {
            float4 e = *reinterpret_cast<const float4*>(&Esh[r * 132 + k4 * 4]);
            acc[r] = fmaf(e.x, w0, acc[r]);
            acc[r] = fmaf(e.y, w1, acc[r]);
            acc[r] = fmaf(e.z, w2, acc[r]);
            acc[r] = fmaf(e.w, w3, acc[r]);
        }
    }
    #pragma unroll
    for (int r = 0; r < 10; ++r)
        d_Y[((size_t)(g * 100 + row0 + r)) * 128 + tid] = sigf(acc[r]);
}

// ---------------- Kernel 2: fused gather + num branch ----------------
// grid (1024 quads, 4 cond-quarters), 512 threads.
// Block = 4 samples x 32-cond quarter:
//  - gather: each Y-row quarter = exactly one 128B line (8 lanes x 16B)
//  - W/b read once per block, reused by 4 samples (quarter-sized)
//  - staging [4][32][128] with XOR swizzle col = g ^ (4*jj): STS banks
//    sub x (rq^jj) all distinct; LDS.128 16B-aligned, phase-bijective.
__global__ __launch_bounds__(512, 3) void fuse_main(
    const float* __restrict__ x_num, const int* __restrict__ x_cat,
    float* __restrict__ out)
{
    extern __shared__ __align__(16) float sh[];   // [4][32][128] = 64 KB
    __shared__ int   s_cat[400];
    __shared__ float s_num[400];

    const int tid  = threadIdx.x;
    const int w    = tid >> 5;
    const int lane = tid & 31;
    const int jj   = lane & 7;     // 16B chunk within 128B line (o-quad 0..7)
    const int sub  = lane >> 3;    // row within quad
    const int b0   = blockIdx.x * 4;
    const int ob   = blockIdx.y * 32;

    if (tid < 400) {
        s_cat[tid] = x_cat[b0 * 100 + tid];
        s_num[tid] = x_num[b0 * 100 + tid];
    }
    __syncthreads();

    // ---- Phase A: gather Y row-quarters -> swizzled transposed staging ----
    // work item: (s, rq): 4 samples x 25 row-quads = 100 warp-iters
    for (int it = w; it < 100; it += 16) {
        int s  = it / 25;
        int rq = it - s * 25;
        int r  = rq * 4 + sub;             // g row 0..99
        int cat = s_cat[s * 100 + r];
        float4 v = *reinterpret_cast<const float4*>(
            &d_Y[(r * 100 + cat) * 128 + ob + jj * 4]);
        int col = r ^ (jj * 4);
        float* dst = &sh[s * 4096 + (jj * 4) * 128 + col];
        dst[0 * 128] = v.x;
        dst[1 * 128] = v.y;
        dst[2 * 128] = v.z;
        dst[3 * 128] = v.w;
    }

    // ---- Phase B: num branch, W/b loaded once, reused for 4 samples ----
    #pragma unroll 2
    for (int idx = tid; idx < 800; idx += 512) {
        int o  = idx / 25;
        int i4 = idx - o * 25;
        float4 ww = *reinterpret_cast<const float4*>(&d_WnumT[(ob + o) * 100 + i4 * 4]);
        float4 bb = *reinterpret_cast<const float4*>(&d_bnumT[(ob + o) * 100 + i4 * 4]);
        #pragma unroll
        for (int s = 0; s < 4; ++s) {
            float4 xs = *reinterpret_cast<const float4*>(&s_num[s * 100 + i4 * 4]);
            float4 r;
            r.x = sig_tanh(fmaf(xs.x, ww.x, bb.x));
            r.y = sig_tanh(fmaf(xs.y, ww.y, bb.y));
            r.z = sig_tanh(fmaf(xs.z, ww.z, bb.z));
            r.w = sig_tanh(fmaf(xs.w, ww.w, bb.w));
            *reinterpret_cast<float4*>(
                &out[(size_t)(b0 + s) * 25600 + (size_t)(ob + o) * 200 + i4 * 4]) = r;
        }
    }
    __syncthreads();

    // ---- Phase C: cat output, swizzled LDS.128 + coalesced STG.128 ----
    #pragma unroll 2
    for (int idx = tid; idx < 3200; idx += 512) {
        int s   = idx / 800;
        int rem = idx - s * 800;
        int o   = rem / 25;
        int g4  = rem - o * 25;
        int colb = (g4 * 4) ^ (o & 28);
        float4 v = *reinterpret_cast<const float4*>(&sh[s * 4096 + o * 128 + colb]);
        *reinterpret_cast<float4*>(
            &out[(size_t)(b0 + s) * 25600 + (size_t)(ob + o) * 200 + 100 + g4 * 4]) = v;
    }
}

extern "C" void kernel_launch(void* const* d_in, const int* in_sizes, int n_in,
                              void* d_out, int out_size) {
    const float* x_num = (const float*)d_in[0];
    const int*   x_cat = (const int*)  d_in[1];
    const float* W_num = (const float*)d_in[2];
    const float* b_num = (const float*)d_in[3];
    const float* emb   = (const float*)d_in[4];
    const float* gn_w  = (const float*)d_in[5];
    const float* gn_b  = (const float*)d_in[6];
    const float* W_cat = (const float*)d_in[7];
    const float* b_cat = (const float*)d_in[8];
    float* out = (float*)d_out;

    const int smem_main = 4 * 32 * 128 * 4;   // 65536 B
    cudaFuncSetAttribute(fuse_main, cudaFuncAttributeMaxDynamicSharedMemorySize, smem_main);

    precompute_Y<<<dim3(100, 11), 128>>>(emb, gn_w, gn_b, W_cat, b_cat, W_num, b_num);
    fuse_main<<<dim3(1024, 4), 512, smem_main>>>(x_num, x_cat, out);
}